// round 8
// baseline (speedup 1.0000x reference)
#include <cuda_runtime.h>
#include <cstdint>

#define L1D 4096
#define L2D 4096
#define NB 8
#define CC 3
#define RSPLIT 4
#define CHUNK (L1D / RSPLIT)   // 1024 refs per CTA
#define QSPLIT 8
#define QCH (L2D / QSPLIT)     // 512 queries per CTA
#define THREADS 128
#define TQ (QCH / THREADS)     // 4 queries per thread
#define TILE 32
#define NTILES (CHUNK / TILE)  // 32

// Scratch for partial (min, idx) per ref-chunk. __device__ globals (no alloc).
__device__ float g_pmin[RSPLIT][NB * L2D];
__device__ int   g_pidx[RSPLIT][NB * L2D];

// ONLY packed op used: fma.rn.f32x2 (proven to execute on this box).
static __device__ __forceinline__ unsigned long long ffma2(
    unsigned long long a, unsigned long long b, unsigned long long c) {
    unsigned long long d;
    asm("fma.rn.f32x2 %0, %1, %2, %3;" : "=l"(d) : "l"(a), "l"(b), "l"(c));
    return d;
}
static __device__ __forceinline__ unsigned long long pack2(float lo, float hi) {
    unsigned long long d;
    asm("mov.b64 %0, {%1, %2};" : "=l"(d) : "f"(lo), "f"(hi));
    return d;
}
static __device__ __forceinline__ void unpack2(unsigned long long v, float& lo, float& hi) {
    asm("mov.b64 {%0, %1}, %2;" : "=f"(lo), "=f"(hi) : "l"(v));
}

// Reference-matching d2 for 2 refs packed, expressed ONLY with fma:
//   dot = fma(qz,rz, fma(qy,ry, fma(qx,rx, +0)))   [== mul then fma chain, k asc]
//   ss  = fma(1, sq, sr)                            [== add.rn(sq, sr)]
//   d2  = fma(-2, dot, ss)                          [== fl(ss - fl(2*dot))]
static __device__ __forceinline__ unsigned long long d2pair(
    unsigned long long qx2, unsigned long long qy2, unsigned long long qz2,
    unsigned long long sq2, unsigned long long x01, unsigned long long y01,
    unsigned long long z01, unsigned long long s01,
    unsigned long long zero2, unsigned long long one2, unsigned long long ntwo2) {
    const unsigned long long dot =
        ffma2(qz2, z01, ffma2(qy2, y01, ffma2(qx2, x01, zero2)));
    return ffma2(ntwo2, dot, ffma2(one2, sq2, s01));
}

// Phase 1: each CTA handles (ref-chunk rs, batch n, query-chunk qc).
// Tracks min d2 per query, records winning 32-ref tile, rescans it with the
// IDENTICAL packed instruction sequence (bitwise-equal) to recover the index.
__global__ __launch_bounds__(THREADS)
void nn_partial(const float* __restrict__ c1, const float* __restrict__ c2) {
    __shared__ __align__(16) float sX[CHUNK];
    __shared__ __align__(16) float sY[CHUNK];
    __shared__ __align__(16) float sZ[CHUNK];
    __shared__ __align__(16) float sS[CHUNK];  // sr = fl(fl(x^2+y^2)+z^2), no fma

    const int b  = blockIdx.x;
    const int qc = b % QSPLIT;
    const int n  = (b / QSPLIT) % NB;
    const int rs = b / (QSPLIT * NB);
    const int t  = threadIdx.x;

    // Stage ref chunk into SoA SMEM. sr uses mul/add WITHOUT fma (matches
    // XLA elementwise-square + reduce, which never contracts across ops).
    for (int i = t; i < CHUNK; i += THREADS) {
        const int l = rs * CHUNK + i;
        const float* p = c1 + (size_t)l * (NB * CC) + n * CC;
        const float x = p[0], y = p[1], z = p[2];
        sX[i] = x; sY[i] = y; sZ[i] = z;
        sS[i] = __fadd_rn(__fadd_rn(__fmul_rn(x, x), __fmul_rn(y, y)),
                          __fmul_rn(z, z));
    }
    __syncthreads();

    // Load TQ queries per thread; pack broadcasts of qx,qy,qz and sq.
    unsigned long long qx2[TQ], qy2[TQ], qz2[TQ], sq2[TQ];
#pragma unroll
    for (int k = 0; k < TQ; k++) {
        const int l2i = qc * QCH + k * THREADS + t;
        const float* p = c2 + (size_t)l2i * (NB * CC) + n * CC;
        const float x = p[0], y = p[1], z = p[2];
        const float sq = __fadd_rn(__fadd_rn(__fmul_rn(x, x), __fmul_rn(y, y)),
                                   __fmul_rn(z, z));
        qx2[k] = pack2(x, x);
        qy2[k] = pack2(y, y);
        qz2[k] = pack2(z, z);
        sq2[k] = pack2(sq, sq);
    }
    const unsigned long long zero2 = pack2(0.0f, 0.0f);
    const unsigned long long one2  = pack2(1.0f, 1.0f);
    const unsigned long long ntwo2 = pack2(-2.0f, -2.0f);

    const float INF = __int_as_float(0x7f800000);
    float m0[TQ], m1[TQ], m2[TQ], m3[TQ], gmin[TQ];
    int wt[TQ];
#pragma unroll
    for (int k = 0; k < TQ; k++) {
        m0[k] = m1[k] = m2[k] = m3[k] = INF;
        gmin[k] = INF;
        wt[k] = 0;
    }

    for (int tile = 0; tile < NTILES; tile++) {
#pragma unroll
        for (int g = 0; g < TILE / 4; g++) {
            const int base = tile * TILE + g * 4;
            // SoA: contiguous floats => LDS.128 yields naturally-packed pairs.
            const float4 xv = *(const float4*)(sX + base);
            const float4 yv = *(const float4*)(sY + base);
            const float4 zv = *(const float4*)(sZ + base);
            const float4 sv = *(const float4*)(sS + base);
            const unsigned long long x01 = pack2(xv.x, xv.y), x23 = pack2(xv.z, xv.w);
            const unsigned long long y01 = pack2(yv.x, yv.y), y23 = pack2(yv.z, yv.w);
            const unsigned long long z01 = pack2(zv.x, zv.y), z23 = pack2(zv.z, zv.w);
            const unsigned long long s01 = pack2(sv.x, sv.y), s23 = pack2(sv.z, sv.w);
#pragma unroll
            for (int k = 0; k < TQ; k++) {
                const unsigned long long d01 =
                    d2pair(qx2[k], qy2[k], qz2[k], sq2[k],
                           x01, y01, z01, s01, zero2, one2, ntwo2);
                const unsigned long long d23 =
                    d2pair(qx2[k], qy2[k], qz2[k], sq2[k],
                           x23, y23, z23, s23, zero2, one2, ntwo2);
                float a0, a1, a2, a3;
                unpack2(d01, a0, a1);
                unpack2(d23, a2, a3);
                m0[k] = fminf(m0[k], a0);
                m1[k] = fminf(m1[k], a1);
                m2[k] = fminf(m2[k], a2);
                m3[k] = fminf(m3[k], a3);
            }
        }
        // m's are running mins: strict '<' vs previous global min fires exactly
        // when THIS tile produced a new global min => first winning tile kept.
#pragma unroll
        for (int k = 0; k < TQ; k++) {
            const float cm = fminf(fminf(m0[k], m1[k]), fminf(m2[k], m3[k]));
            if (cm < gmin[k]) { wt[k] = tile; gmin[k] = cm; }
        }
    }

    // Phase 1b: rescan winning tile with the IDENTICAL packed recompute
    // (same instructions, same inputs -> bitwise equal). Ascending scan,
    // first match kept => first-index argmin semantics.
    int bidx[TQ];
#pragma unroll
    for (int k = 0; k < TQ; k++) {
        const float cm = gmin[k];
        int idx = -1;
        const int s0 = wt[k] * TILE;
#pragma unroll
        for (int g = 0; g < TILE / 4; g++) {
            const int base = s0 + g * 4;
            const float4 xv = *(const float4*)(sX + base);
            const float4 yv = *(const float4*)(sY + base);
            const float4 zv = *(const float4*)(sZ + base);
            const float4 sv = *(const float4*)(sS + base);
            const unsigned long long x01 = pack2(xv.x, xv.y), x23 = pack2(xv.z, xv.w);
            const unsigned long long y01 = pack2(yv.x, yv.y), y23 = pack2(yv.z, yv.w);
            const unsigned long long z01 = pack2(zv.x, zv.y), z23 = pack2(zv.z, zv.w);
            const unsigned long long s01 = pack2(sv.x, sv.y), s23 = pack2(sv.z, sv.w);
            const unsigned long long d01 =
                d2pair(qx2[k], qy2[k], qz2[k], sq2[k],
                       x01, y01, z01, s01, zero2, one2, ntwo2);
            const unsigned long long d23 =
                d2pair(qx2[k], qy2[k], qz2[k], sq2[k],
                       x23, y23, z23, s23, zero2, one2, ntwo2);
            float a0, a1, a2, a3;
            unpack2(d01, a0, a1);
            unpack2(d23, a2, a3);
            if (idx < 0 && a0 == cm) idx = rs * CHUNK + base + 0;
            if (idx < 0 && a1 == cm) idx = rs * CHUNK + base + 1;
            if (idx < 0 && a2 == cm) idx = rs * CHUNK + base + 2;
            if (idx < 0 && a3 == cm) idx = rs * CHUNK + base + 3;
        }
        bidx[k] = (idx < 0) ? (rs * CHUNK + s0) : idx;  // fallback unreachable
    }

#pragma unroll
    for (int k = 0; k < TQ; k++) {
        const int l2i = qc * QCH + k * THREADS + t;
        const int gq = n * L2D + l2i;
        g_pmin[rs][gq] = gmin[k];
        g_pidx[rs][gq] = bidx[k];
    }
}

// Phase 2: combine the RSPLIT partials (ascending chunk order, strict '<'
// => first index on exact cross-chunk ties). Output dtype is FLOAT32:
// indices <= 4095 are exactly representable.
__global__ void nn_combine(float* __restrict__ out) {
    const int gq = blockIdx.x * blockDim.x + threadIdx.x;  // n*L2 + l2
    if (gq >= NB * L2D) return;
    const int n = gq / L2D;
    const int l2i = gq % L2D;
    float best = g_pmin[0][gq];
    int bi = g_pidx[0][gq];
#pragma unroll
    for (int rs = 1; rs < RSPLIT; rs++) {
        const float v = g_pmin[rs][gq];
        if (v < best) { best = v; bi = g_pidx[rs][gq]; }
    }
    out[l2i * NB + n] = (float)bi;                // clusters, [L2, N] flat
    out[NB * L2D + l2i * NB + n] = (float)n;      // batch indices, [L2, N] flat
}

extern "C" void kernel_launch(void* const* d_in, const int* in_sizes, int n_in,
                              void* d_out, int out_size) {
    const float* c1 = (const float*)d_in[0];  // coords1 [L1, N, C]
    const float* c2 = (const float*)d_in[1];  // coords2 [L2, N, C]
    float* out = (float*)d_out;

    nn_partial<<<RSPLIT * NB * QSPLIT, THREADS>>>(c1, c2);
    nn_combine<<<(NB * L2D + 255) / 256, 256>>>(out);
}

// round 9
// speedup vs baseline: 1.0050x; 1.0050x over previous
#include <cuda_runtime.h>
#include <cstdint>

#define L1D 4096
#define L2D 4096
#define NB 8
#define CC 3
#define RSPLIT 8
#define CHUNK (L1D / RSPLIT)   // 512 refs per unit
#define QSPLIT 16
#define QCH (L2D / QSPLIT)     // 256 queries per unit
#define THREADS 64
#define TQ (QCH / THREADS)     // 4 queries per thread
#define TILE 32
#define NTILES (CHUNK / TILE)  // 16
#define TOT (NB * L2D)         // 32768 query slots

// Packed partials: [gq = l2i*NB + n][rs] -> (f32 d2 bits << 32) | idx.
// Row-major 64B rows => combine reads are fully coalesced vector loads.
__device__ unsigned long long g_p[TOT][RSPLIT];

// ONLY packed op used: fma.rn.f32x2 (proven on this box; mul/add.f32x2 hung).
static __device__ __forceinline__ unsigned long long ffma2(
    unsigned long long a, unsigned long long b, unsigned long long c) {
    unsigned long long d;
    asm("fma.rn.f32x2 %0, %1, %2, %3;" : "=l"(d) : "l"(a), "l"(b), "l"(c));
    return d;
}
static __device__ __forceinline__ unsigned long long pack2(float lo, float hi) {
    unsigned long long d;
    asm("mov.b64 %0, {%1, %2};" : "=l"(d) : "f"(lo), "f"(hi));
    return d;
}
static __device__ __forceinline__ void unpack2(unsigned long long v, float& lo, float& hi) {
    asm("mov.b64 {%0, %1}, %2;" : "=f"(lo), "=f"(hi) : "l"(v));
}

// Reference-matching d2 for 2 refs packed, expressed ONLY with fma:
//   dot = fma(qz,rz, fma(qy,ry, fma(qx,rx, +0)))   [mul-then-fma chain, k asc]
//   ss  = fma(1, sq, sr)                            [== add.rn(sq, sr)]
//   d2  = fma(-2, dot, ss)                          [== fl(ss - fl(2*dot))]
static __device__ __forceinline__ unsigned long long d2pair(
    unsigned long long qx2, unsigned long long qy2, unsigned long long qz2,
    unsigned long long sq2, unsigned long long x01, unsigned long long y01,
    unsigned long long z01, unsigned long long s01,
    unsigned long long zero2, unsigned long long one2, unsigned long long ntwo2) {
    const unsigned long long dot =
        ffma2(qz2, z01, ffma2(qy2, y01, ffma2(qx2, x01, zero2)));
    return ffma2(ntwo2, dot, ffma2(one2, sq2, s01));
}

// Phase 1: unit = (ref-chunk rs, batch n, query-chunk qc). Tracks min d2 per
// query, records winning 32-ref tile, rescans it with the IDENTICAL packed
// instruction sequence (bitwise-equal) to recover the first-index argmin.
__global__ __launch_bounds__(THREADS)
void nn_partial(const float* __restrict__ c1, const float* __restrict__ c2) {
    __shared__ __align__(16) float sX[CHUNK];
    __shared__ __align__(16) float sY[CHUNK];
    __shared__ __align__(16) float sZ[CHUNK];
    __shared__ __align__(16) float sS[CHUNK];  // sr = fl(fl(x^2+y^2)+z^2), no fma

    const int b  = blockIdx.x;
    const int qc = b % QSPLIT;
    const int n  = (b / QSPLIT) % NB;
    const int rs = b / (QSPLIT * NB);
    const int t  = threadIdx.x;

    // Stage ref chunk into SoA SMEM. sr uses mul/add WITHOUT fma (matches
    // XLA elementwise-square + reduce, which never contracts across ops).
    for (int i = t; i < CHUNK; i += THREADS) {
        const int l = rs * CHUNK + i;
        const float* p = c1 + (size_t)l * (NB * CC) + n * CC;
        const float x = p[0], y = p[1], z = p[2];
        sX[i] = x; sY[i] = y; sZ[i] = z;
        sS[i] = __fadd_rn(__fadd_rn(__fmul_rn(x, x), __fmul_rn(y, y)),
                          __fmul_rn(z, z));
    }
    __syncthreads();

    // Load TQ queries per thread; pack broadcasts of qx,qy,qz and sq.
    unsigned long long qx2[TQ], qy2[TQ], qz2[TQ], sq2[TQ];
#pragma unroll
    for (int k = 0; k < TQ; k++) {
        const int l2i = qc * QCH + k * THREADS + t;
        const float* p = c2 + (size_t)l2i * (NB * CC) + n * CC;
        const float x = p[0], y = p[1], z = p[2];
        const float sq = __fadd_rn(__fadd_rn(__fmul_rn(x, x), __fmul_rn(y, y)),
                                   __fmul_rn(z, z));
        qx2[k] = pack2(x, x);
        qy2[k] = pack2(y, y);
        qz2[k] = pack2(z, z);
        sq2[k] = pack2(sq, sq);
    }
    const unsigned long long zero2 = pack2(0.0f, 0.0f);
    const unsigned long long one2  = pack2(1.0f, 1.0f);
    const unsigned long long ntwo2 = pack2(-2.0f, -2.0f);

    const float INF = __int_as_float(0x7f800000);
    float m0[TQ], m1[TQ], m2[TQ], m3[TQ], gmin[TQ];
    int wt[TQ];
#pragma unroll
    for (int k = 0; k < TQ; k++) {
        m0[k] = m1[k] = m2[k] = m3[k] = INF;
        gmin[k] = INF;
        wt[k] = 0;
    }

    for (int tile = 0; tile < NTILES; tile++) {
#pragma unroll
        for (int g = 0; g < TILE / 4; g++) {
            const int base = tile * TILE + g * 4;
            // SoA: contiguous floats => LDS.128 yields naturally-packed pairs.
            const float4 xv = *(const float4*)(sX + base);
            const float4 yv = *(const float4*)(sY + base);
            const float4 zv = *(const float4*)(sZ + base);
            const float4 sv = *(const float4*)(sS + base);
            const unsigned long long x01 = pack2(xv.x, xv.y), x23 = pack2(xv.z, xv.w);
            const unsigned long long y01 = pack2(yv.x, yv.y), y23 = pack2(yv.z, yv.w);
            const unsigned long long z01 = pack2(zv.x, zv.y), z23 = pack2(zv.z, zv.w);
            const unsigned long long s01 = pack2(sv.x, sv.y), s23 = pack2(sv.z, sv.w);
#pragma unroll
            for (int k = 0; k < TQ; k++) {
                const unsigned long long d01 =
                    d2pair(qx2[k], qy2[k], qz2[k], sq2[k],
                           x01, y01, z01, s01, zero2, one2, ntwo2);
                const unsigned long long d23 =
                    d2pair(qx2[k], qy2[k], qz2[k], sq2[k],
                           x23, y23, z23, s23, zero2, one2, ntwo2);
                float a0, a1, a2, a3;
                unpack2(d01, a0, a1);
                unpack2(d23, a2, a3);
                m0[k] = fminf(m0[k], a0);
                m1[k] = fminf(m1[k], a1);
                m2[k] = fminf(m2[k], a2);
                m3[k] = fminf(m3[k], a3);
            }
        }
        // m's are running mins: strict '<' vs previous global min fires exactly
        // when THIS tile produced a new global min => first winning tile kept.
#pragma unroll
        for (int k = 0; k < TQ; k++) {
            const float cm = fminf(fminf(m0[k], m1[k]), fminf(m2[k], m3[k]));
            if (cm < gmin[k]) { wt[k] = tile; gmin[k] = cm; }
        }
    }

    // Phase 1b: rescan winning tile with the IDENTICAL packed recompute
    // (same instructions, same inputs -> bitwise equal). Ascending scan,
    // first match kept => first-index argmin semantics.
    int bidx[TQ];
#pragma unroll
    for (int k = 0; k < TQ; k++) {
        const float cm = gmin[k];
        int idx = -1;
        const int s0 = wt[k] * TILE;
#pragma unroll
        for (int g = 0; g < TILE / 4; g++) {
            const int base = s0 + g * 4;
            const float4 xv = *(const float4*)(sX + base);
            const float4 yv = *(const float4*)(sY + base);
            const float4 zv = *(const float4*)(sZ + base);
            const float4 sv = *(const float4*)(sS + base);
            const unsigned long long x01 = pack2(xv.x, xv.y), x23 = pack2(xv.z, xv.w);
            const unsigned long long y01 = pack2(yv.x, yv.y), y23 = pack2(yv.z, yv.w);
            const unsigned long long z01 = pack2(zv.x, zv.y), z23 = pack2(zv.z, zv.w);
            const unsigned long long s01 = pack2(sv.x, sv.y), s23 = pack2(sv.z, sv.w);
            const unsigned long long d01 =
                d2pair(qx2[k], qy2[k], qz2[k], sq2[k],
                       x01, y01, z01, s01, zero2, one2, ntwo2);
            const unsigned long long d23 =
                d2pair(qx2[k], qy2[k], qz2[k], sq2[k],
                       x23, y23, z23, s23, zero2, one2, ntwo2);
            float a0, a1, a2, a3;
            unpack2(d01, a0, a1);
            unpack2(d23, a2, a3);
            if (idx < 0 && a0 == cm) idx = rs * CHUNK + base + 0;
            if (idx < 0 && a1 == cm) idx = rs * CHUNK + base + 1;
            if (idx < 0 && a2 == cm) idx = rs * CHUNK + base + 2;
            if (idx < 0 && a3 == cm) idx = rs * CHUNK + base + 3;
        }
        bidx[k] = (idx < 0) ? (rs * CHUNK + s0) : idx;  // fallback unreachable
    }

    // Store packed (d2 bits, idx) at [l2i*NB + n][rs] (output-ordered rows).
#pragma unroll
    for (int k = 0; k < TQ; k++) {
        const int l2i = qc * QCH + k * THREADS + t;
        const int gq = l2i * NB + n;
        g_p[gq][rs] = ((unsigned long long)__float_as_uint(gmin[k]) << 32) |
                      (unsigned int)bidx[k];
    }
}

// Phase 2: combine RSPLIT partials per query. Thread i == output slot i
// (i = l2i*NB + n) -> coalesced 64B row reads + coalesced output stores.
// Ascending rs with strict '<' => first index on exact cross-chunk ties.
__global__ __launch_bounds__(256)
void nn_combine(float* __restrict__ out) {
    const int i = blockIdx.x * blockDim.x + threadIdx.x;
    if (i >= TOT) return;
    const ulonglong4* row = (const ulonglong4*)(&g_p[i][0]);
    const ulonglong4 v0 = row[0];
    const ulonglong4 v1 = row[1];
    unsigned long long vs[RSPLIT] = {v0.x, v0.y, v0.z, v0.w, v1.x, v1.y, v1.z, v1.w};
    float best = __uint_as_float((unsigned int)(vs[0] >> 32));
    int bi = (int)(unsigned int)vs[0];
#pragma unroll
    for (int rs = 1; rs < RSPLIT; rs++) {
        const float v = __uint_as_float((unsigned int)(vs[rs] >> 32));
        if (v < best) { best = v; bi = (int)(unsigned int)vs[rs]; }
    }
    out[i] = (float)bi;                 // clusters, [L2, N] flat
    out[TOT + i] = (float)(i & (NB - 1));  // batch index n, [L2, N] flat
}

extern "C" void kernel_launch(void* const* d_in, const int* in_sizes, int n_in,
                              void* d_out, int out_size) {
    const float* c1 = (const float*)d_in[0];  // coords1 [L1, N, C]
    const float* c2 = (const float*)d_in[1];  // coords2 [L2, N, C]
    float* out = (float*)d_out;

    nn_partial<<<RSPLIT * NB * QSPLIT, THREADS>>>(c1, c2);
    nn_combine<<<TOT / 256, 256>>>(out);
}